// round 10
// baseline (speedup 1.0000x reference)
#include <cuda_runtime.h>
#include <math.h>

// ---------------------------------------------------------------------------
// Problem constants
// ---------------------------------------------------------------------------
#define BB    2
#define NN    1024
#define DIMM  512
#define HEADS 8
#define DH    64
#define INNER 512          // HEADS*DH
#define FF    2048         // DIM*4
#define ROWS  (BB*NN)      // 2048
#define EPS   1e-6f
#define ATT_SCALE 0.125f   // DH^-0.5

// plane stride for planar q/k/v and attn buffers: B*H*N*DH = 2*8*1024*64
#define PLANE (1u<<20)

// ---------------------------------------------------------------------------
// Scratch (device globals; no allocation allowed)
// ---------------------------------------------------------------------------
__device__ float g_x  [ROWS*DIMM*2];      // running residual (complex interleaved)
__device__ float g_h  [ROWS*DIMM*2];      // rmsnorm output
__device__ float g_q  [ROWS*INNER*2];     // q = h @ Wq
__device__ float g_kv [ROWS*2*INNER*2];   // kv = h @ Wkv
__device__ float g_qp [2*PLANE];          // planar [comp][b][h][n][dh], rope applied
__device__ float g_kp [2*PLANE];
__device__ float g_vp [2*PLANE];
__device__ float g_attn[4*PLANE];         // 4 variants (rr, ri, ir, ii)
__device__ float g_o  [ROWS*INNER*2];     // combined complex attention output
__device__ float g_ff [ROWS*FF*2];        // feed-forward hidden

// ---------------------------------------------------------------------------
// copy kernel (x -> g_x), float4
// ---------------------------------------------------------------------------
__global__ void copy_kernel(const float4* __restrict__ src, float4* __restrict__ dst, int n4)
{
    int i = blockIdx.x * blockDim.x + threadIdx.x;
    if (i < n4) dst[i] = src[i];
}

// ---------------------------------------------------------------------------
// RMSNorm over complex last dim (DIM), times complex gamma
// one block per row, 256 threads
// ---------------------------------------------------------------------------
__global__ void rmsnorm_kernel(const float* __restrict__ x,
                               const float* __restrict__ gamma,
                               float* __restrict__ out)
{
    int row = blockIdx.x;
    const float* xr = x + (size_t)row * (DIMM*2);
    float* orow = out + (size_t)row * (DIMM*2);
    __shared__ float red[256];
    int tid = threadIdx.x;
    float s = 0.f;
    for (int e = tid; e < DIMM; e += 256) {
        float a = xr[2*e], b = xr[2*e+1];
        s += a*a + b*b;
    }
    red[tid] = s;
    __syncthreads();
    for (int off = 128; off > 0; off >>= 1) {
        if (tid < off) red[tid] += red[tid + off];
        __syncthreads();
    }
    float ms = red[0] * (1.f / DIMM);
    float sc = 1.f / sqrtf(ms + EPS);
    for (int e = tid; e < DIMM; e += 256) {
        float a = xr[2*e] * sc, b = xr[2*e+1] * sc;
        float gr = gamma[2*e], gi = gamma[2*e+1];
        orow[2*e]   = a*gr - b*gi;
        orow[2*e+1] = a*gi + b*gr;
    }
}

// ---------------------------------------------------------------------------
// Complex GEMM as real GEMM: C(M x 2Nc) = A(M x 2Kc) * Breal(2Kc x 2Nc)
// Breal[2k+p][2n+q] = {(0,0):Wr, (0,1):Wi, (1,0):-Wi, (1,1):Wr}.
// Templated on tile-N (BN = 64 or 128). 128xBNx16 tiles, 256 threads,
// 8 x (BN/16) register tile, double-buffered smem.
// GRID CONTRACT (enforced at every call site): grid.x = 2*Nc / BN,
//                                              grid.y = M / 128.
// ---------------------------------------------------------------------------
template<int BN>
__global__ void __launch_bounds__(256)
cgemm_kernel(const float* __restrict__ A,
             const float* __restrict__ W,
             const float* __restrict__ bias,
             const float* __restrict__ resid,
             float* __restrict__ C,
             int M, int Kc, int Nc)
{
    constexpr int TN = BN / 16;    // per-thread output cols (4 or 8)
    const int K  = 2*Kc;
    const int Nr = 2*Nc;
    __shared__ float As[2][16][128];
    __shared__ float Bs[2][16][BN];

    int t  = threadIdx.x;          // 0..255
    int tx = t & 15;               // output col group
    int ty = t >> 4;               // output row group (8 rows each)
    int row0 = blockIdx.y * 128;
    int col0 = blockIdx.x * BN;

    int ar = t >> 2;               // 0..63  (A staging row within half-tile)
    int ac = (t & 3) * 4;          // 0,4,8,12

    // B staging: slab is 8 complex-k rows x (BN/2) complex cols
    int kcl = t >> 5;              // 0..7
    int ncl = (BN == 128) ? (t & 31) * 2 : (t & 31);
    const int nc0 = col0 >> 1;     // complex col base

    float acc[8][TN];
#pragma unroll
    for (int i = 0; i < 8; i++)
#pragma unroll
        for (int j = 0; j < TN; j++) acc[i][j] = 0.f;

    float4 av0, av1;
    float4 wv4;
    float2 wv2;
    auto load_tile = [&](int k0) {
        av0 = *(const float4*)&A[(size_t)(row0 + ar) * K + k0 + ac];
        av1 = *(const float4*)&A[(size_t)(row0 + 64 + ar) * K + k0 + ac];
        int kc = (k0 >> 1) + kcl;
        if constexpr (BN == 128)
            wv4 = *(const float4*)&W[((size_t)kc * Nc + nc0 + ncl) * 2];
        else
            wv2 = *(const float2*)&W[((size_t)kc * Nc + nc0 + ncl) * 2];
    };
    auto store_tile = [&](int buf) {
        As[buf][ac+0][ar]      = av0.x;
        As[buf][ac+1][ar]      = av0.y;
        As[buf][ac+2][ar]      = av0.z;
        As[buf][ac+3][ar]      = av0.w;
        As[buf][ac+0][64 + ar] = av1.x;
        As[buf][ac+1][64 + ar] = av1.y;
        As[buf][ac+2][64 + ar] = av1.z;
        As[buf][ac+3][64 + ar] = av1.w;
        if constexpr (BN == 128) {
            // two complex weights -> 2x4 real block
            *(float4*)&Bs[buf][2*kcl    ][2*ncl] = make_float4( wv4.x, wv4.y,  wv4.z, wv4.w);
            *(float4*)&Bs[buf][2*kcl + 1][2*ncl] = make_float4(-wv4.y, wv4.x, -wv4.w, wv4.z);
        } else {
            *(float2*)&Bs[buf][2*kcl    ][2*ncl] = make_float2( wv2.x, wv2.y);
            *(float2*)&Bs[buf][2*kcl + 1][2*ncl] = make_float2(-wv2.y, wv2.x);
        }
    };

    // prologue: stage slab 0
    load_tile(0);
    store_tile(0);
    __syncthreads();

    int buf = 0;
    for (int k0 = 0; k0 < K; k0 += 16) {
        bool has_next = (k0 + 16) < K;
        if (has_next) load_tile(k0 + 16);   // global loads overlap compute below

#pragma unroll
        for (int kk = 0; kk < 16; kk++) {
            float a[8], b[TN];
            *(float4*)&a[0] = *(const float4*)&As[buf][kk][ty*8];
            *(float4*)&a[4] = *(const float4*)&As[buf][kk][ty*8 + 4];
#pragma unroll
            for (int j = 0; j < TN; j += 4)
                *(float4*)&b[j] = *(const float4*)&Bs[buf][kk][tx*TN + j];
#pragma unroll
            for (int i = 0; i < 8; i++)
#pragma unroll
                for (int j = 0; j < TN; j++)
                    acc[i][j] += a[i] * b[j];
        }

        if (has_next) {
            store_tile(buf ^ 1);
            __syncthreads();
            buf ^= 1;
        }
    }

    // epilogue: float4 stores
    float bv[TN];
#pragma unroll
    for (int j = 0; j < TN; j++) bv[j] = 0.f;
    if (bias) {
#pragma unroll
        for (int j = 0; j < TN; j += 4)
            *(float4*)&bv[j] = *(const float4*)&bias[col0 + tx*TN + j];
    }
#pragma unroll
    for (int i = 0; i < 8; i++) {
        int r = row0 + ty*8 + i;
#pragma unroll
        for (int j = 0; j < TN; j += 4) {
            float4 v = make_float4(acc[i][j] + bv[j],   acc[i][j+1] + bv[j+1],
                                   acc[i][j+2] + bv[j+2], acc[i][j+3] + bv[j+3]);
            if (resid) {
                float4 rv = *(const float4*)&resid[(size_t)r * Nr + col0 + tx*TN + j];
                v.x += rv.x; v.y += rv.y; v.z += rv.z; v.w += rv.w;
            }
            *(float4*)&C[(size_t)r * Nr + col0 + tx*TN + j] = v;
        }
    }
}

// ---------------------------------------------------------------------------
// RoPE + planar split.
// ---------------------------------------------------------------------------
__global__ void rope_split_kernel(const float* __restrict__ q,
                                  const float* __restrict__ kv,
                                  float* __restrict__ qp,
                                  float* __restrict__ kp,
                                  float* __restrict__ vp)
{
    int idx = blockIdx.x * blockDim.x + threadIdx.x;   // over B*N*INNER = 2^20
    if (idx >= BB*NN*INNER) return;
    int e = idx & (INNER-1);
    int n = (idx >> 9) & (NN-1);
    int b = idx >> 19;
    int h = e >> 6, dh = e & 63;

    // invfreq = 10000^(-dh/64)
    float invf = expf((float)dh * (-9.210340371976184f / 64.f));
    float ang = (float)n * invf;
    float sn, cs;
    sincosf(ang, &sn, &cs);

    size_t po = ((size_t)(b*HEADS + h) * NN + n) * DH + dh;

    // q
    {
        float r = q[(size_t)idx*2], im = q[(size_t)idx*2 + 1];
        qp[po]         = r*cs - im*sn;
        qp[po + PLANE] = r*sn + im*cs;
    }
    // k (first INNER cols of kv)
    {
        size_t kvi = ((size_t)(b*NN + n) * (2*INNER) + e) * 2;
        float r = kv[kvi], im = kv[kvi + 1];
        kp[po]         = r*cs - im*sn;
        kp[po + PLANE] = r*sn + im*cs;
    }
    // v (second INNER cols), no rope
    {
        size_t kvi = ((size_t)(b*NN + n) * (2*INNER) + INNER + e) * 2;
        vp[po]         = kv[kvi];
        vp[po + PLANE] = kv[kvi + 1];
    }
}

// ---------------------------------------------------------------------------
// Flash attention over one (variant, b, h): 4 variants
//   v0: attend(qr, kr, vr)   v1: attend(qr,-ki, vr)
//   v2: attend(qi, kr, vi)   v3: attend(qi,-ki, vi)
// ---------------------------------------------------------------------------
__global__ void __launch_bounds__(64)
attn_kernel(const float* __restrict__ qp,
            const float* __restrict__ kp,
            const float* __restrict__ vp,
            float* __restrict__ outp)
{
    int vbh = blockIdx.y;
    int v   = vbh >> 4;
    int bh  = vbh & 15;
    int qc  = (v < 2) ? 0 : 1;
    int kc  = v & 1;
    float ksign = (v & 1) ? -1.f : 1.f;
    int vc  = qc;

    int tid = threadIdx.x;                 // 0..63
    int nq  = blockIdx.x * 64 + tid;

    __shared__ float Ks[64][64];
    __shared__ float Vs[64][64];

    const float* qrow = qp + (size_t)qc * PLANE + ((size_t)bh * NN + nq) * DH;
    float q[64];
#pragma unroll
    for (int d = 0; d < 64; d += 4) {
        float4 t4 = *(const float4*)&qrow[d];
        q[d]   = t4.x * ATT_SCALE;
        q[d+1] = t4.y * ATT_SCALE;
        q[d+2] = t4.z * ATT_SCALE;
        q[d+3] = t4.w * ATT_SCALE;
    }

    float o[64];
#pragma unroll
    for (int d = 0; d < 64; d++) o[d] = 0.f;
    float m = -1e30f, l = 0.f;

    const float* kbase = kp + (size_t)kc * PLANE + (size_t)bh * NN * DH;
    const float* vbase = vp + (size_t)vc * PLANE + (size_t)bh * NN * DH;

    for (int k0 = 0; k0 < NN; k0 += 64) {
        __syncthreads();
#pragma unroll 4
        for (int i = 0; i < 64; i++) {
            Ks[i][tid] = ksign * kbase[(size_t)(k0 + i) * DH + tid];
            Vs[i][tid] =         vbase[(size_t)(k0 + i) * DH + tid];
        }
        __syncthreads();

        for (int c = 0; c < 4; c++) {
            float s[16];
#pragma unroll
            for (int jj = 0; jj < 16; jj++) {
                const float* kr = Ks[c*16 + jj];
                float a = 0.f;
#pragma unroll
                for (int d = 0; d < 64; d++) a += q[d] * kr[d];
                s[jj] = a;
            }
            float mt = m;
#pragma unroll
            for (int jj = 0; jj < 16; jj++) mt = fmaxf(mt, s[jj]);
            float alpha = __expf(m - mt);
            m = mt;
            l *= alpha;
#pragma unroll
            for (int d = 0; d < 64; d++) o[d] *= alpha;
#pragma unroll
            for (int jj = 0; jj < 16; jj++) {
                float p = __expf(s[jj] - mt);
                l += p;
                const float* vr = Vs[c*16 + jj];
#pragma unroll
                for (int d = 0; d < 64; d++) o[d] += p * vr[d];
            }
        }
    }

    float inv = 1.f / l;
    float* orow = outp + (size_t)v * PLANE + ((size_t)bh * NN + nq) * DH;
#pragma unroll
    for (int d = 0; d < 64; d++) orow[d] = o[d] * inv;
}

// ---------------------------------------------------------------------------
// Combine 4 attention planes to complex (B,N,INNER,2):
//   re = rr - ii, im = ri + ir
// ---------------------------------------------------------------------------
__global__ void combine_kernel(const float* __restrict__ attn, float* __restrict__ o)
{
    int idx = blockIdx.x * blockDim.x + threadIdx.x;   // over B*N*INNER
    if (idx >= BB*NN*INNER) return;
    int e = idx & (INNER-1);
    int n = (idx >> 9) & (NN-1);
    int b = idx >> 19;
    int h = e >> 6, dh = e & 63;
    size_t a = ((size_t)(b*HEADS + h) * NN + n) * DH + dh;
    float rr = attn[a];
    float ri = attn[a + (size_t)1*PLANE];
    float ir = attn[a + (size_t)2*PLANE];
    float ii = attn[a + (size_t)3*PLANE];
    o[(size_t)idx*2]     = rr - ii;
    o[(size_t)idx*2 + 1] = ri + ir;
}

// ---------------------------------------------------------------------------
// FF nonlinearity: h <- relu(|h| + mod_bias)^2 * exp(i*angle(h))
// ---------------------------------------------------------------------------
__global__ void ffact_kernel(float* __restrict__ h, const float* __restrict__ mod_bias, int l)
{
    int idx = blockIdx.x * blockDim.x + threadIdx.x;   // over B*N*FF
    if (idx >= BB*NN*FF) return;
    float mb = mod_bias[l];
    float hr = h[(size_t)idx*2], hi = h[(size_t)idx*2 + 1];
    float mag = sqrtf(hr*hr + hi*hi);
    float t = mag + mb;
    float c = (t > 0.f) ? t*t : 0.f;
    float orr, oi;
    if (mag > 0.f) {
        float s = c / mag;
        orr = hr * s; oi = hi * s;
    } else {
        orr = c; oi = 0.f;
    }
    h[(size_t)idx*2]     = orr;
    h[(size_t)idx*2 + 1] = oi;
}

// ---------------------------------------------------------------------------
// Launch
// ---------------------------------------------------------------------------
extern "C" void kernel_launch(void* const* d_in, const int* in_sizes, int n_in,
                              void* d_out, int out_size)
{
    const float* x          = (const float*)d_in[0];
    const float* gamma_attn = (const float*)d_in[1];
    const float* Wq         = (const float*)d_in[2];
    const float* Wkv        = (const float*)d_in[3];
    const float* Wo         = (const float*)d_in[4];
    const float* gamma_ff   = (const float*)d_in[5];
    const float* W1         = (const float*)d_in[6];
    const float* b1         = (const float*)d_in[7];
    const float* mod_bias   = (const float*)d_in[8];
    const float* W2         = (const float*)d_in[9];
    const float* b2         = (const float*)d_in[10];
    const float* gamma_fin  = (const float*)d_in[11];

    float *gx, *gh, *gq, *gkv, *gqp, *gkp, *gvp, *gattn, *go, *gff;
    cudaGetSymbolAddress((void**)&gx,   g_x);
    cudaGetSymbolAddress((void**)&gh,   g_h);
    cudaGetSymbolAddress((void**)&gq,   g_q);
    cudaGetSymbolAddress((void**)&gkv,  g_kv);
    cudaGetSymbolAddress((void**)&gqp,  g_qp);
    cudaGetSymbolAddress((void**)&gkp,  g_kp);
    cudaGetSymbolAddress((void**)&gvp,  g_vp);
    cudaGetSymbolAddress((void**)&gattn,g_attn);
    cudaGetSymbolAddress((void**)&go,   g_o);
    cudaGetSymbolAddress((void**)&gff,  g_ff);

    // x -> g_x
    {
        int n4 = ROWS*DIMM*2/4;
        copy_kernel<<<(n4 + 255)/256, 256>>>((const float4*)x, (float4*)gx, n4);
    }

    const int ew_blocks  = (BB*NN*INNER + 255)/256;   // 4096
    const int ff_blocks  = (BB*NN*FF + 255)/256;      // 16384

    for (int l = 0; l < 2; l++) {
        // attention block
        rmsnorm_kernel<<<ROWS, 256>>>(gx, gamma_attn + l*DIMM*2, gh);
        // Wq: Nr = 2*INNER = 1024 -> BN=64: grid.x = 1024/64 = 16; grid.y = 2048/128 = 16
        cgemm_kernel<64><<<dim3(16, 16), 256>>>(gh, Wq  + (size_t)l*DIMM*INNER*2,
                                                nullptr, nullptr, gq, ROWS, DIMM, INNER);
        // Wkv: Nr = 2*(2*INNER) = 2048 -> BN=128: grid.x = 2048/128 = 16
        cgemm_kernel<128><<<dim3(16, 16), 256>>>(gh, Wkv + (size_t)l*DIMM*2*INNER*2,
                                                 nullptr, nullptr, gkv, ROWS, DIMM, 2*INNER);
        rope_split_kernel<<<ew_blocks, 256>>>(gq, gkv, gqp, gkp, gvp);
        attn_kernel<<<dim3(16, 64), 64>>>(gqp, gkp, gvp, gattn);
        combine_kernel<<<ew_blocks, 256>>>(gattn, go);
        // Wo: Nr = 2*DIMM = 1024 -> BN=64: grid.x = 16
        cgemm_kernel<64><<<dim3(16, 16), 256>>>(go, Wo + (size_t)l*INNER*DIMM*2,
                                                nullptr, gx, gx, ROWS, INNER, DIMM);
        // feed-forward block
        rmsnorm_kernel<<<ROWS, 256>>>(gx, gamma_ff + l*DIMM*2, gh);
        // W1: Nr = 2*FF = 4096 -> BN=128: grid.x = 4096/128 = 32
        cgemm_kernel<128><<<dim3(32, 16), 256>>>(gh, W1 + (size_t)l*DIMM*FF*2,
                                                 b1 + (size_t)l*FF*2, nullptr, gff, ROWS, DIMM, FF);
        ffact_kernel<<<ff_blocks, 256>>>(gff, mod_bias, l);
        // W2: Nr = 2*DIMM = 1024 -> BN=64: grid.x = 16
        cgemm_kernel<64><<<dim3(16, 16), 256>>>(gff, W2 + (size_t)l*FF*DIMM*2,
                                                b2 + (size_t)l*DIMM*2, gx, gx, ROWS, FF, DIMM);
    }

    rmsnorm_kernel<<<ROWS, 256>>>(gx, gamma_fin, (float*)d_out);
}

// round 16
// speedup vs baseline: 1.2420x; 1.2420x over previous
#include <cuda_runtime.h>
#include <cuda_bf16.h>
#include <math.h>
#include <stdint.h>

// ---------------------------------------------------------------------------
// Problem constants
// ---------------------------------------------------------------------------
#define BB    2
#define NN    1024
#define DIMM  512
#define HEADS 8
#define DH    64
#define INNER 512          // HEADS*DH
#define FF    2048         // DIM*4
#define ROWS  (BB*NN)      // 2048
#define EPS   1e-6f
#define ATT_SCALE 0.125f   // DH^-0.5
#define PLANE (1u<<20)     // B*H*N*DH

// ---------------------------------------------------------------------------
// Scratch (device globals; no allocation allowed)
// ---------------------------------------------------------------------------
__device__ float g_x  [ROWS*DIMM*2];
__device__ float g_h  [ROWS*DIMM*2];
__device__ float g_q  [ROWS*INNER*2];
__device__ float g_kv [ROWS*2*INNER*2];
__device__ float g_qp [2*PLANE];
__device__ float g_kp [2*PLANE];
__device__ float g_vp [2*PLANE];
__device__ float g_attn[4*PLANE];
__device__ float g_o  [ROWS*INNER*2];
__device__ float g_ff [ROWS*FF*2];

// ---------------------------------------------------------------------------
// bf16 helpers
// ---------------------------------------------------------------------------
__device__ __forceinline__ void bf16_split(float x, uint32_t& h, uint32_t& l)
{
    __nv_bfloat16 hb = __float2bfloat16_rn(x);
    float r = x - __bfloat162float(hb);
    __nv_bfloat16 lb = __float2bfloat16_rn(r);
    h = (uint32_t)__bfloat16_as_ushort(hb);
    l = (uint32_t)__bfloat16_as_ushort(lb);
}

// mma.sync m16n8k16 row.col f32.bf16.bf16.f32  (sm_80+ baseline; no 'a' target)
__device__ __forceinline__ void mma_bf16(float* d, const uint32_t* a, const uint32_t* b)
{
    asm volatile(
        "mma.sync.aligned.m16n8k16.row.col.f32.bf16.bf16.f32 "
        "{%0,%1,%2,%3}, {%4,%5,%6,%7}, {%8,%9}, {%0,%1,%2,%3};\n"
        : "+f"(d[0]), "+f"(d[1]), "+f"(d[2]), "+f"(d[3])
        : "r"(a[0]), "r"(a[1]), "r"(a[2]), "r"(a[3]), "r"(b[0]), "r"(b[1]));
}

// ---------------------------------------------------------------------------
// copy kernel (x -> g_x), float4
// ---------------------------------------------------------------------------
__global__ void copy_kernel(const float4* __restrict__ src, float4* __restrict__ dst, int n4)
{
    int i = blockIdx.x * blockDim.x + threadIdx.x;
    if (i < n4) dst[i] = src[i];
}

// ---------------------------------------------------------------------------
// RMSNorm over complex last dim (DIM), times complex gamma
// ---------------------------------------------------------------------------
__global__ void rmsnorm_kernel(const float* __restrict__ x,
                               const float* __restrict__ gamma,
                               float* __restrict__ out)
{
    int row = blockIdx.x;
    const float* xr = x + (size_t)row * (DIMM*2);
    float* orow = out + (size_t)row * (DIMM*2);
    __shared__ float red[256];
    int tid = threadIdx.x;
    float s = 0.f;
    for (int e = tid; e < DIMM; e += 256) {
        float a = xr[2*e], b = xr[2*e+1];
        s += a*a + b*b;
    }
    red[tid] = s;
    __syncthreads();
    for (int off = 128; off > 0; off >>= 1) {
        if (tid < off) red[tid] += red[tid + off];
        __syncthreads();
    }
    float ms = red[0] * (1.f / DIMM);
    float sc = 1.f / sqrtf(ms + EPS);
    for (int e = tid; e < DIMM; e += 256) {
        float a = xr[2*e] * sc, b = xr[2*e+1] * sc;
        float gr = gamma[2*e], gi = gamma[2*e+1];
        orow[2*e]   = a*gr - b*gi;
        orow[2*e+1] = a*gi + b*gr;
    }
}

// ---------------------------------------------------------------------------
// Tensor-core complex GEMM via mma.sync (bf16 hi/lo error-compensated).
// C(M x 2Nc) = A(M x 2Kc) @ Breal(2Kc x 2Nc).
// Staged B is Breal transposed ([n][k], k-contiguous = "col" operand):
//   row 2nc:   k=2kc -> Wr,  k=2kc+1 -> -Wi
//   row 2nc+1: k=2kc -> Wi,  k=2kc+1 ->  Wr
// Tile: 128(M) x 64(N), K-slab 32 bf16 (16 complex k). 256 threads, 8 warps
// in a 4(M) x 2(N) grid; warp tile 32x32 = 2 m16 x 4 n8 fragments.
// Per k16-step, 3 compensated products: AhBh + AhBl + AlBh.
// GRID CONTRACT: grid.x = 2*Nc/64, grid.y = M/128.
// ---------------------------------------------------------------------------
__global__ void __launch_bounds__(256)
cgemm_mma(const float* __restrict__ A,
          const float* __restrict__ W,
          const float* __restrict__ bias,
          const float* __restrict__ resid,
          float* __restrict__ C,
          int M, int Kc, int Nc)
{
    // padded stride 40 uint16 (80B): fragment-load word index g*20+tig mod 32
    // hits 32 distinct banks -> conflict-free
    __shared__ __align__(16) uint16_t sAh[128][40];
    __shared__ __align__(16) uint16_t sAl[128][40];
    __shared__ __align__(16) uint16_t sBh[64][40];
    __shared__ __align__(16) uint16_t sBl[64][40];

    const int K  = 2*Kc;
    const int Nr = 2*Nc;
    int t    = threadIdx.x;
    int wid  = t >> 5;
    int lane = t & 31;
    int g    = lane >> 2;          // fragment group row 0..7
    int tig  = lane & 3;           // thread-in-group 0..3
    int row0 = blockIdx.y * 128;
    int col0 = blockIdx.x * 64;
    const int nc0 = col0 >> 1;

    int wm = (wid & 3) * 32;       // warp M offset within tile
    int wn = (wid >> 2) * 32;      // warp N offset within tile

    // A staging: thread -> row t>>1 (0..127), half t&1 -> k base half*16
    int arow  = t >> 1;
    int ahalf = t & 1;
    // B staging: thread -> complex col t%32, complex k rows t/32 + {0,8}
    int ncl = t & 31;
    int kcb = t >> 5;

    float acc[2][4][4];
#pragma unroll
    for (int mt = 0; mt < 2; mt++)
#pragma unroll
        for (int nt = 0; nt < 4; nt++)
#pragma unroll
            for (int i = 0; i < 4; i++) acc[mt][nt][i] = 0.f;

    const int nslab = Kc >> 4;     // 16 complex k (32 bf16) per slab
    for (int s = 0; s < nslab; s++) {
        int k0r = s * 32;
        int kc0 = s * 16;

        // ---- stage A: 128 x 32 fp32 -> bf16 hi/lo ----
        {
            const float* arp = A + (size_t)(row0 + arow) * K + k0r + ahalf*16;
            int kb = ahalf * 16;
#pragma unroll
            for (int i = 0; i < 4; i++) {
                float4 v = *(const float4*)(arp + i*4);
                uint32_t h0,l0,h1,l1,h2,l2,h3,l3;
                bf16_split(v.x, h0, l0);
                bf16_split(v.y, h1, l1);
                bf16_split(v.z, h2, l2);
                bf16_split(v.w, h3, l3);
                *(uint32_t*)&sAh[arow][kb + i*4]     = h0 | (h1<<16);
                *(uint32_t*)&sAh[arow][kb + i*4 + 2] = h2 | (h3<<16);
                *(uint32_t*)&sAl[arow][kb + i*4]     = l0 | (l1<<16);
                *(uint32_t*)&sAl[arow][kb + i*4 + 2] = l2 | (l3<<16);
            }
        }

        // ---- stage B: 16(kc) x 32(nc) complex weights -> expanded hi/lo ----
#pragma unroll
        for (int j = 0; j < 2; j++) {
            int kcl = kcb + j*8;   // 0..15
            float2 w = *(const float2*)&W[((size_t)(kc0 + kcl) * Nc + nc0 + ncl) * 2];
            uint32_t hr, lr, hi, li;
            bf16_split(w.x, hr, lr);           // Wr
            bf16_split(w.y, hi, li);           // Wi
            uint32_t hmi = hi ^ 0x8000u;       // -Wi
            uint32_t lmi = li ^ 0x8000u;
            *(uint32_t*)&sBh[2*ncl  ][2*kcl] = hr | (hmi<<16);  // (Wr, -Wi)
            *(uint32_t*)&sBl[2*ncl  ][2*kcl] = lr | (lmi<<16);
            *(uint32_t*)&sBh[2*ncl+1][2*kcl] = hi | (hr <<16);  // (Wi,  Wr)
            *(uint32_t*)&sBl[2*ncl+1][2*kcl] = li | (lr <<16);
        }
        __syncthreads();

        // ---- MMAs: 2 k16-steps x (2 m-tiles x 4 n-tiles) x 3 products ----
#pragma unroll
        for (int ks = 0; ks < 2; ks++) {
            int kk = ks * 16;
            // B fragments for this warp's 4 n-tiles
            uint32_t Bh[4][2], Bl[4][2];
#pragma unroll
            for (int nt = 0; nt < 4; nt++) {
                int n = wn + nt*8 + g;
                Bh[nt][0] = *(const uint32_t*)&sBh[n][kk + tig*2];
                Bh[nt][1] = *(const uint32_t*)&sBh[n][kk + tig*2 + 8];
                Bl[nt][0] = *(const uint32_t*)&sBl[n][kk + tig*2];
                Bl[nt][1] = *(const uint32_t*)&sBl[n][kk + tig*2 + 8];
            }
#pragma unroll
            for (int mt = 0; mt < 2; mt++) {
                int m = wm + mt*16;
                uint32_t Ah[4], Al[4];
                Ah[0] = *(const uint32_t*)&sAh[m + g    ][kk + tig*2];
                Ah[1] = *(const uint32_t*)&sAh[m + g + 8][kk + tig*2];
                Ah[2] = *(const uint32_t*)&sAh[m + g    ][kk + tig*2 + 8];
                Ah[3] = *(const uint32_t*)&sAh[m + g + 8][kk + tig*2 + 8];
                Al[0] = *(const uint32_t*)&sAl[m + g    ][kk + tig*2];
                Al[1] = *(const uint32_t*)&sAl[m + g + 8][kk + tig*2];
                Al[2] = *(const uint32_t*)&sAl[m + g    ][kk + tig*2 + 8];
                Al[3] = *(const uint32_t*)&sAl[m + g + 8][kk + tig*2 + 8];
#pragma unroll
                for (int nt = 0; nt < 4; nt++) {
                    mma_bf16(acc[mt][nt], Ah, Bh[nt]);
                    mma_bf16(acc[mt][nt], Ah, Bl[nt]);
                    mma_bf16(acc[mt][nt], Al, Bh[nt]);
                }
            }
        }
        __syncthreads();
    }

    // ---- epilogue ----
#pragma unroll
    for (int mt = 0; mt < 2; mt++) {
        int rb = row0 + wm + mt*16;
#pragma unroll
        for (int nt = 0; nt < 4; nt++) {
            int c = col0 + wn + nt*8 + tig*2;
            float2 v0 = make_float2(acc[mt][nt][0], acc[mt][nt][1]);  // row rb+g
            float2 v1 = make_float2(acc[mt][nt][2], acc[mt][nt][3]);  // row rb+g+8
            if (bias) {
                float2 bv = *(const float2*)&bias[c];
                v0.x += bv.x; v0.y += bv.y;
                v1.x += bv.x; v1.y += bv.y;
            }
            if (resid) {
                float2 r0 = *(const float2*)&resid[(size_t)(rb + g    ) * Nr + c];
                float2 r1 = *(const float2*)&resid[(size_t)(rb + g + 8) * Nr + c];
                v0.x += r0.x; v0.y += r0.y;
                v1.x += r1.x; v1.y += r1.y;
            }
            *(float2*)&C[(size_t)(rb + g    ) * Nr + c] = v0;
            *(float2*)&C[(size_t)(rb + g + 8) * Nr + c] = v1;
        }
    }
}

// ---------------------------------------------------------------------------
// RoPE + planar split.
// ---------------------------------------------------------------------------
__global__ void rope_split_kernel(const float* __restrict__ q,
                                  const float* __restrict__ kv,
                                  float* __restrict__ qp,
                                  float* __restrict__ kp,
                                  float* __restrict__ vp)
{
    int idx = blockIdx.x * blockDim.x + threadIdx.x;
    if (idx >= BB*NN*INNER) return;
    int e = idx & (INNER-1);
    int n = (idx >> 9) & (NN-1);
    int b = idx >> 19;
    int h = e >> 6, dh = e & 63;

    float invf = expf((float)dh * (-9.210340371976184f / 64.f));
    float ang = (float)n * invf;
    float sn, cs;
    sincosf(ang, &sn, &cs);

    size_t po = ((size_t)(b*HEADS + h) * NN + n) * DH + dh;

    {
        float r = q[(size_t)idx*2], im = q[(size_t)idx*2 + 1];
        qp[po]         = r*cs - im*sn;
        qp[po + PLANE] = r*sn + im*cs;
    }
    {
        size_t kvi = ((size_t)(b*NN + n) * (2*INNER) + e) * 2;
        float r = kv[kvi], im = kv[kvi + 1];
        kp[po]         = r*cs - im*sn;
        kp[po + PLANE] = r*sn + im*cs;
    }
    {
        size_t kvi = ((size_t)(b*NN + n) * (2*INNER) + INNER + e) * 2;
        vp[po]         = kv[kvi];
        vp[po + PLANE] = kv[kvi + 1];
    }
}

// ---------------------------------------------------------------------------
// Flash attention over one (variant, b, h)
// ---------------------------------------------------------------------------
__global__ void __launch_bounds__(64)
attn_kernel(const float* __restrict__ qp,
            const float* __restrict__ kp,
            const float* __restrict__ vp,
            float* __restrict__ outp)
{
    int vbh = blockIdx.y;
    int v   = vbh >> 4;
    int bh  = vbh & 15;
    int qc  = (v < 2) ? 0 : 1;
    int kc  = v & 1;
    float ksign = (v & 1) ? -1.f : 1.f;
    int vc  = qc;

    int tid = threadIdx.x;
    int nq  = blockIdx.x * 64 + tid;

    __shared__ float Ks[64][64];
    __shared__ float Vs[64][64];

    const float* qrow = qp + (size_t)qc * PLANE + ((size_t)bh * NN + nq) * DH;
    float q[64];
#pragma unroll
    for (int d = 0; d < 64; d += 4) {
        float4 t4 = *(const float4*)&qrow[d];
        q[d]   = t4.x * ATT_SCALE;
        q[d+1] = t4.y * ATT_SCALE;
        q[d+2] = t4.z * ATT_SCALE;
        q[d+3] = t4.w * ATT_SCALE;
    }

    float o[64];
#pragma unroll
    for (int d = 0; d < 64; d++) o[d] = 0.f;
    float m = -1e30f, l = 0.f;

    const float* kbase = kp + (size_t)kc * PLANE + (size_t)bh * NN * DH;
    const float* vbase = vp + (size_t)vc * PLANE + (size_t)bh * NN * DH;

    for (int k0 = 0; k0 < NN; k0 += 64) {
        __syncthreads();
#pragma unroll 4
        for (int i = 0; i < 64; i++) {
            Ks[i][tid] = ksign * kbase[(size_t)(k0 + i) * DH + tid];
            Vs[i][tid] =         vbase[(size_t)(k0 + i) * DH + tid];
        }
        __syncthreads();

        for (int c = 0; c < 4; c++) {
            float s[16];
#pragma unroll
            for (int jj = 0; jj < 16; jj++) {
                const float* kr = Ks[c*16 + jj];
                float a = 0.f;
#pragma unroll
                for (int d = 0; d < 64; d++) a += q[d] * kr[d];
                s[jj] = a;
            }
            float mt = m;
#pragma unroll
            for (int jj = 0; jj < 16; jj++) mt = fmaxf(mt, s[jj]);
            float alpha = __expf(m - mt);
            m = mt;
            l *= alpha;
#pragma unroll
            for (int d = 0; d < 64; d++) o[d] *= alpha;
#pragma unroll
            for (int jj = 0; jj < 16; jj++) {
                float p = __expf(s[jj] - mt);
                l += p;
                const float* vr = Vs[c*16 + jj];
#pragma unroll
                for (int d = 0; d < 64; d++) o[d] += p * vr[d];
            }
        }
    }

    float inv = 1.f / l;
    float* orow = outp + (size_t)v * PLANE + ((size_t)bh * NN + nq) * DH;
#pragma unroll
    for (int d = 0; d < 64; d++) orow[d] = o[d] * inv;
}

// ---------------------------------------------------------------------------
// Combine 4 attention planes to complex
// ---------------------------------------------------------------------------
__global__ void combine_kernel(const float* __restrict__ attn, float* __restrict__ o)
{
    int idx = blockIdx.x * blockDim.x + threadIdx.x;
    if (idx >= BB*NN*INNER) return;
    int e = idx & (INNER-1);
    int n = (idx >> 9) & (NN-1);
    int b = idx >> 19;
    int h = e >> 6, dh = e & 63;
    size_t a = ((size_t)(b*HEADS + h) * NN + n) * DH + dh;
    float rr = attn[a];
    float ri = attn[a + (size_t)1*PLANE];
    float ir = attn[a + (size_t)2*PLANE];
    float ii = attn[a + (size_t)3*PLANE];
    o[(size_t)idx*2]     = rr - ii;
    o[(size_t)idx*2 + 1] = ri + ir;
}

// ---------------------------------------------------------------------------
// FF nonlinearity
// ---------------------------------------------------------------------------
__global__ void ffact_kernel(float* __restrict__ h, const float* __restrict__ mod_bias, int l)
{
    int idx = blockIdx.x * blockDim.x + threadIdx.x;
    if (idx >= BB*NN*FF) return;
    float mb = mod_bias[l];
    float hr = h[(size_t)idx*2], hi = h[(size_t)idx*2 + 1];
    float mag = sqrtf(hr*hr + hi*hi);
    float t = mag + mb;
    float c = (t > 0.f) ? t*t : 0.f;
    float orr, oi;
    if (mag > 0.f) {
        float s = c / mag;
        orr = hr * s; oi = hi * s;
    } else {
        orr = c; oi = 0.f;
    }
    h[(size_t)idx*2]     = orr;
    h[(size_t)idx*2 + 1] = oi;
}

// ---------------------------------------------------------------------------
// Launch
// ---------------------------------------------------------------------------
extern "C" void kernel_launch(void* const* d_in, const int* in_sizes, int n_in,
                              void* d_out, int out_size)
{
    const float* x          = (const float*)d_in[0];
    const float* gamma_attn = (const float*)d_in[1];
    const float* Wq         = (const float*)d_in[2];
    const float* Wkv        = (const float*)d_in[3];
    const float* Wo         = (const float*)d_in[4];
    const float* gamma_ff   = (const float*)d_in[5];
    const float* W1         = (const float*)d_in[6];
    const float* b1         = (const float*)d_in[7];
    const float* mod_bias   = (const float*)d_in[8];
    const float* W2         = (const float*)d_in[9];
    const float* b2         = (const float*)d_in[10];
    const float* gamma_fin  = (const float*)d_in[11];

    float *gx, *gh, *gq, *gkv, *gqp, *gkp, *gvp, *gattn, *go, *gff;
    cudaGetSymbolAddress((void**)&gx,   g_x);
    cudaGetSymbolAddress((void**)&gh,   g_h);
    cudaGetSymbolAddress((void**)&gq,   g_q);
    cudaGetSymbolAddress((void**)&gkv,  g_kv);
    cudaGetSymbolAddress((void**)&gqp,  g_qp);
    cudaGetSymbolAddress((void**)&gkp,  g_kp);
    cudaGetSymbolAddress((void**)&gvp,  g_vp);
    cudaGetSymbolAddress((void**)&gattn,g_attn);
    cudaGetSymbolAddress((void**)&go,   g_o);
    cudaGetSymbolAddress((void**)&gff,  g_ff);

    // x -> g_x
    {
        int n4 = ROWS*DIMM*2/4;
        copy_kernel<<<(n4 + 255)/256, 256>>>((const float4*)x, (float4*)gx, n4);
    }

    const int ew_blocks  = (BB*NN*INNER + 255)/256;   // 4096
    const int ff_blocks  = (BB*NN*FF + 255)/256;      // 16384

    for (int l = 0; l < 2; l++) {
        // attention block
        rmsnorm_kernel<<<ROWS, 256>>>(gx, gamma_attn + l*DIMM*2, gh);
        // Wq: Nr=1024 -> grid(16,16)
        cgemm_mma<<<dim3(16, 16), 256>>>(gh, Wq  + (size_t)l*DIMM*INNER*2,
                                         nullptr, nullptr, gq, ROWS, DIMM, INNER);
        // Wkv: Nr=2048 -> grid(32,16)
        cgemm_mma<<<dim3(32, 16), 256>>>(gh, Wkv + (size_t)l*DIMM*2*INNER*2,
                                         nullptr, nullptr, gkv, ROWS, DIMM, 2*INNER);
        rope_split_kernel<<<ew_blocks, 256>>>(gq, gkv, gqp, gkp, gvp);
        attn_kernel<<<dim3(16, 64), 64>>>(gqp, gkp, gvp, gattn);
        combine_kernel<<<ew_blocks, 256>>>(gattn, go);
        // Wo: Nr=1024 -> grid(16,16)
        cgemm_mma<<<dim3(16, 16), 256>>>(go, Wo + (size_t)l*INNER*DIMM*2,
                                         nullptr, gx, gx, ROWS, INNER, DIMM);
        // feed-forward block
        rmsnorm_kernel<<<ROWS, 256>>>(gx, gamma_ff + l*DIMM*2, gh);
        // W1: Nr=4096 -> grid(64,16)
        cgemm_mma<<<dim3(64, 16), 256>>>(gh, W1 + (size_t)l*DIMM*FF*2,
                                         b1 + (size_t)l*FF*2, nullptr, gff, ROWS, DIMM, FF);
        ffact_kernel<<<ff_blocks, 256>>>(gff, mod_bias, l);
        // W2: Nr=1024, Kc=2048 -> grid(16,16)
        cgemm_mma<<<dim3(16, 16), 256>>>(gff, W2 + (size_t)l*FF*DIMM*2,
                                         b2 + (size_t)l*DIMM*2, gx, gx, ROWS, FF, DIMM);
    }

    rmsnorm_kernel<<<ROWS, 256>>>(gx, gamma_fin, (float*)d_out);
}